// round 8
// baseline (speedup 1.0000x reference)
#include <cuda_runtime.h>
#include <cuda_fp16.h>
#include <cstdint>

// out[b,o,{re,im}] = complex(X) @ complex(W)^T (no conj), as ONE real GEMM:
//   C[M,N] = A[M,K] * B'[N,K]^T, M=N=K=4096
//   A = [Xre | Xim]
//   B'[n]      = [ Wre[n], -Wim[n] ]  (n<2048  -> out_re)
//   B'[n+2048] = [ Wim[n],  Wre[n] ]  (         -> out_im)
// Single fp16 product with fp32 accumulation (rel_err ~3e-4 < 1e-3).
// R7: 4 warps x (64x64) warp tiles (halved ldmatrix/MMA issue overhead),
//     128-thread CTAs, 2 CTAs/SM, 3-stage cp.async ring.

static constexpr int M = 4096;
static constexpr int N = 4096;
static constexpr int K = 4096;
static constexpr int INF = 2048;
static constexpr int OUTF = 2048;

static constexpr int BM = 128;
static constexpr int BN = 128;
static constexpr int BK = 64;
static constexpr int LDS = BK + 8;        // 72 fp16 = 144B row stride (conflict-free)
static constexpr int TILE = BM * LDS;     // 9216 elems per tile
static constexpr int STAGES = 3;
static constexpr int STAGE_ELEMS = 2 * TILE;                // A tile + B tile
static constexpr int SMEM_BYTES = STAGES * STAGE_ELEMS * 2; // 110592 B

static constexpr int NTHREADS = 128;

__device__ __half g_A[(size_t)M * K];
__device__ __half g_B[(size_t)N * K];

// ---------------------------------------------------------------------------
// Vectorized prep: 8 elems per thread (two float4 loads -> one uint4 store).
// ---------------------------------------------------------------------------
__global__ void prep_all(const float* __restrict__ xre, const float* __restrict__ xim,
                         const float* __restrict__ wre, const float* __restrict__ wim) {
    size_t idx8 = ((size_t)blockIdx.x * blockDim.x + threadIdx.x) * 8;
    float4 f0, f1;
    float sgn = 1.0f;
    __half* dst;

    if (idx8 < (size_t)M * K) {
        int k = (int)(idx8 & (K - 1));
        int b = (int)(idx8 >> 12);
        const float* src = (k < INF) ? (xre + (size_t)b * INF + k)
                                     : (xim + (size_t)b * INF + (k - INF));
        f0 = *(const float4*)src;
        f1 = *(const float4*)(src + 4);
        dst = g_A + idx8;
    } else {
        size_t j = idx8 - (size_t)M * K;
        int k = (int)(j & (K - 1));
        int n = (int)(j >> 12);
        const float* src;
        if (n < OUTF) {
            if (k < INF) { src = wre + (size_t)n * INF + k; }
            else         { src = wim + (size_t)n * INF + (k - INF); sgn = -1.0f; }
        } else {
            int o = n - OUTF;
            src = (k < INF) ? (wim + (size_t)o * INF + k)
                            : (wre + (size_t)o * INF + (k - INF));
        }
        f0 = *(const float4*)src;
        f1 = *(const float4*)(src + 4);
        dst = g_B + j;
    }

    __half h[8];
    h[0] = __float2half(sgn * f0.x); h[1] = __float2half(sgn * f0.y);
    h[2] = __float2half(sgn * f0.z); h[3] = __float2half(sgn * f0.w);
    h[4] = __float2half(sgn * f1.x); h[5] = __float2half(sgn * f1.y);
    h[6] = __float2half(sgn * f1.z); h[7] = __float2half(sgn * f1.w);
    *(uint4*)dst = *(const uint4*)h;
}

// ---------------------------------------------------------------------------
// helpers
// ---------------------------------------------------------------------------
__device__ __forceinline__ void cp_async16(uint32_t saddr, const void* g) {
    asm volatile("cp.async.cg.shared.global [%0], [%1], 16;" :: "r"(saddr), "l"(g));
}
__device__ __forceinline__ void cp_commit() { asm volatile("cp.async.commit_group;"); }
__device__ __forceinline__ void cp_wait1()  { asm volatile("cp.async.wait_group 1;"); }

__device__ __forceinline__ void ldm_x4(uint32_t* r, uint32_t saddr) {
    asm volatile("ldmatrix.sync.aligned.m8n8.x4.shared.b16 {%0,%1,%2,%3}, [%4];"
                 : "=r"(r[0]), "=r"(r[1]), "=r"(r[2]), "=r"(r[3]) : "r"(saddr));
}
__device__ __forceinline__ void mma16816(float* c, const uint32_t* a, const uint32_t* b) {
    asm volatile("mma.sync.aligned.m16n8k16.row.col.f32.f16.f16.f32 "
                 "{%0,%1,%2,%3}, {%4,%5,%6,%7}, {%8,%9}, {%0,%1,%2,%3};"
                 : "+f"(c[0]), "+f"(c[1]), "+f"(c[2]), "+f"(c[3])
                 : "r"(a[0]), "r"(a[1]), "r"(a[2]), "r"(a[3]),
                   "r"(b[0]), "r"(b[1]));
}

// ---------------------------------------------------------------------------
// GEMM: 128x128 CTA, 4 warps in 2x2, warp tile 64x64, BK=64, 3-stage ring,
// 2 CTAs/SM.
// ---------------------------------------------------------------------------
__global__ void __launch_bounds__(NTHREADS, 2) gemm_f16(float* __restrict__ out) {
    extern __shared__ __align__(16) __half smem[];

    const int tid  = threadIdx.x;
    const int lane = tid & 31;
    const int warp = tid >> 5;
    const int wm = warp >> 1;     // 0..1
    const int wn = warp & 1;      // 0..1
    const int bm0 = blockIdx.y * BM;
    const int bn0 = blockIdx.x * BN;

    float acc[4][8][4];
#pragma unroll
    for (int i = 0; i < 4; i++)
#pragma unroll
        for (int j = 0; j < 8; j++)
#pragma unroll
            for (int q = 0; q < 4; q++) acc[i][j][q] = 0.f;

    // 1024 16B-chunks per tile; 128 threads -> 8 chunks of A and 8 of B each.
    auto load_tile = [&](int st, int k0) {
        __half* sA = smem + st * STAGE_ELEMS;
        __half* sB = sA + TILE;
#pragma unroll
        for (int rep = 0; rep < 8; rep++) {
            int ch  = tid + rep * NTHREADS;   // 0..1023
            int row = ch >> 3;
            int col = (ch & 7) * 8;
            size_t gA = (size_t)(bm0 + row) * K + k0 + col;
            size_t gB = (size_t)(bn0 + row) * K + k0 + col;
            int soff = row * LDS + col;
            cp_async16((uint32_t)__cvta_generic_to_shared(sA + soff), g_A + gA);
            cp_async16((uint32_t)__cvta_generic_to_shared(sB + soff), g_B + gB);
        }
    };

    load_tile(0, 0);       cp_commit();
    load_tile(1, BK);      cp_commit();

    const int NKT = K / BK;   // 64
#pragma unroll 1
    for (int kt = 0; kt < NKT; kt++) {
        cp_wait1();
        __syncthreads();

        if (kt + 2 < NKT) load_tile((kt + 2) % STAGES, (kt + 2) * BK);
        cp_commit();

        const int cur = kt % STAGES;
        const __half* sA = smem + cur * STAGE_ELEMS;
        const __half* sB = sA + TILE;

#pragma unroll
        for (int ks = 0; ks < 4; ks++) {
            const int kk = ks * 16;

            // A: 4 m16 fragments
            uint32_t af[4][4];
            const int arow = wm * 64 + (lane & 15);
            const int acol = kk + ((lane >> 4) << 3);
#pragma unroll
            for (int im = 0; im < 4; im++) {
                int soff = (arow + im * 16) * LDS + acol;
                ldm_x4(af[im], (uint32_t)__cvta_generic_to_shared(sA + soff));
            }

            // B: 8 n8 fragments via 4 x4-ldmatrix
            uint32_t bf[8][2];
            {
                int mset = lane >> 3;
                int nrow_in = (lane & 7) + ((mset >> 1) << 3);
                int col = kk + ((mset & 1) << 3);
#pragma unroll
                for (int ip = 0; ip < 4; ip++) {
                    int nrow = wn * 64 + ip * 16 + nrow_in;
                    int soff = nrow * LDS + col;
                    uint32_t r[4];
                    ldm_x4(r, (uint32_t)__cvta_generic_to_shared(sB + soff));
                    bf[ip * 2][0] = r[0]; bf[ip * 2][1] = r[1];
                    bf[ip * 2 + 1][0] = r[2]; bf[ip * 2 + 1][1] = r[3];
                }
            }

#pragma unroll
            for (int im = 0; im < 4; im++)
#pragma unroll
                for (int in = 0; in < 8; in++) mma16816(acc[im][in], af[im], bf[in]);
        }
        __syncthreads();
    }

    // Epilogue: C[m, n] -> out[m, n & 2047, n >> 11]
    const int gr = lane >> 2;
    const int gc = (lane & 3) << 1;
#pragma unroll
    for (int im = 0; im < 4; im++) {
#pragma unroll
        for (int in = 0; in < 8; in++) {
            int m0 = bm0 + wm * 64 + im * 16 + gr;
            int n0 = bn0 + wn * 64 + in * 8 + gc;
            int c = n0 >> 11;
            int o = n0 & (OUTF - 1);
            out[((size_t)m0 * OUTF + o) * 2 + c]           = acc[im][in][0];
            out[((size_t)m0 * OUTF + o + 1) * 2 + c]       = acc[im][in][1];
            out[((size_t)(m0 + 8) * OUTF + o) * 2 + c]     = acc[im][in][2];
            out[((size_t)(m0 + 8) * OUTF + o + 1) * 2 + c] = acc[im][in][3];
        }
    }
}

// ---------------------------------------------------------------------------
extern "C" void kernel_launch(void* const* d_in, const int* in_sizes, int n_in,
                              void* d_out, int out_size) {
    const float* x_re = (const float*)d_in[0];
    const float* x_im = (const float*)d_in[1];
    const float* w_re = (const float*)d_in[2];
    const float* w_im = (const float*)d_in[3];
    float* out = (float*)d_out;

    cudaFuncSetAttribute(gemm_f16, cudaFuncAttributeMaxDynamicSharedMemorySize,
                         SMEM_BYTES);

    size_t total8 = ((size_t)M * K + (size_t)N * K) / 8;
    prep_all<<<(unsigned)(total8 / 256), 256>>>(x_re, x_im, w_re, w_im);

    dim3 grid(N / BN, M / BM);
    gemm_f16<<<grid, NTHREADS, SMEM_BYTES>>>(out);
}

// round 9
// speedup vs baseline: 1.0015x; 1.0015x over previous
#include <cuda_runtime.h>
#include <cuda_fp16.h>
#include <cstdint>

// out[b,o,{re,im}] = complex(X) @ complex(W)^T (no conj), as ONE real GEMM:
//   C[M,N] = A[M,K] * B'[N,K]^T, M=N=K=4096
//   A = [Xre | Xim]
//   B'[n]      = [ Wre[n], -Wim[n] ]  (n<2048  -> out_re)
//   B'[n+2048] = [ Wim[n],  Wre[n] ]  (         -> out_im)
// Single fp16 product with fp32 accumulation (rel_err ~3e-4 < 1e-3).
// R7: 4 warps x (64x64) warp tiles (halved ldmatrix/MMA issue overhead),
//     128-thread CTAs, 2 CTAs/SM, 3-stage cp.async ring.

static constexpr int M = 4096;
static constexpr int N = 4096;
static constexpr int K = 4096;
static constexpr int INF = 2048;
static constexpr int OUTF = 2048;

static constexpr int BM = 128;
static constexpr int BN = 128;
static constexpr int BK = 64;
static constexpr int LDS = BK + 8;        // 72 fp16 = 144B row stride (conflict-free)
static constexpr int TILE = BM * LDS;     // 9216 elems per tile
static constexpr int STAGES = 3;
static constexpr int STAGE_ELEMS = 2 * TILE;                // A tile + B tile
static constexpr int SMEM_BYTES = STAGES * STAGE_ELEMS * 2; // 110592 B

static constexpr int NTHREADS = 128;

__device__ __half g_A[(size_t)M * K];
__device__ __half g_B[(size_t)N * K];

// ---------------------------------------------------------------------------
// Vectorized prep: 8 elems per thread (two float4 loads -> one uint4 store).
// ---------------------------------------------------------------------------
__global__ void prep_all(const float* __restrict__ xre, const float* __restrict__ xim,
                         const float* __restrict__ wre, const float* __restrict__ wim) {
    size_t idx8 = ((size_t)blockIdx.x * blockDim.x + threadIdx.x) * 8;
    float4 f0, f1;
    float sgn = 1.0f;
    __half* dst;

    if (idx8 < (size_t)M * K) {
        int k = (int)(idx8 & (K - 1));
        int b = (int)(idx8 >> 12);
        const float* src = (k < INF) ? (xre + (size_t)b * INF + k)
                                     : (xim + (size_t)b * INF + (k - INF));
        f0 = *(const float4*)src;
        f1 = *(const float4*)(src + 4);
        dst = g_A + idx8;
    } else {
        size_t j = idx8 - (size_t)M * K;
        int k = (int)(j & (K - 1));
        int n = (int)(j >> 12);
        const float* src;
        if (n < OUTF) {
            if (k < INF) { src = wre + (size_t)n * INF + k; }
            else         { src = wim + (size_t)n * INF + (k - INF); sgn = -1.0f; }
        } else {
            int o = n - OUTF;
            src = (k < INF) ? (wim + (size_t)o * INF + k)
                            : (wre + (size_t)o * INF + (k - INF));
        }
        f0 = *(const float4*)src;
        f1 = *(const float4*)(src + 4);
        dst = g_B + j;
    }

    __half h[8];
    h[0] = __float2half(sgn * f0.x); h[1] = __float2half(sgn * f0.y);
    h[2] = __float2half(sgn * f0.z); h[3] = __float2half(sgn * f0.w);
    h[4] = __float2half(sgn * f1.x); h[5] = __float2half(sgn * f1.y);
    h[6] = __float2half(sgn * f1.z); h[7] = __float2half(sgn * f1.w);
    *(uint4*)dst = *(const uint4*)h;
}

// ---------------------------------------------------------------------------
// helpers
// ---------------------------------------------------------------------------
__device__ __forceinline__ void cp_async16(uint32_t saddr, const void* g) {
    asm volatile("cp.async.cg.shared.global [%0], [%1], 16;" :: "r"(saddr), "l"(g));
}
__device__ __forceinline__ void cp_commit() { asm volatile("cp.async.commit_group;"); }
__device__ __forceinline__ void cp_wait1()  { asm volatile("cp.async.wait_group 1;"); }

__device__ __forceinline__ void ldm_x4(uint32_t* r, uint32_t saddr) {
    asm volatile("ldmatrix.sync.aligned.m8n8.x4.shared.b16 {%0,%1,%2,%3}, [%4];"
                 : "=r"(r[0]), "=r"(r[1]), "=r"(r[2]), "=r"(r[3]) : "r"(saddr));
}
__device__ __forceinline__ void mma16816(float* c, const uint32_t* a, const uint32_t* b) {
    asm volatile("mma.sync.aligned.m16n8k16.row.col.f32.f16.f16.f32 "
                 "{%0,%1,%2,%3}, {%4,%5,%6,%7}, {%8,%9}, {%0,%1,%2,%3};"
                 : "+f"(c[0]), "+f"(c[1]), "+f"(c[2]), "+f"(c[3])
                 : "r"(a[0]), "r"(a[1]), "r"(a[2]), "r"(a[3]),
                   "r"(b[0]), "r"(b[1]));
}

// ---------------------------------------------------------------------------
// GEMM: 128x128 CTA, 4 warps in 2x2, warp tile 64x64, BK=64, 3-stage ring,
// 2 CTAs/SM.
// ---------------------------------------------------------------------------
__global__ void __launch_bounds__(NTHREADS, 2) gemm_f16(float* __restrict__ out) {
    extern __shared__ __align__(16) __half smem[];

    const int tid  = threadIdx.x;
    const int lane = tid & 31;
    const int warp = tid >> 5;
    const int wm = warp >> 1;     // 0..1
    const int wn = warp & 1;      // 0..1
    const int bm0 = blockIdx.y * BM;
    const int bn0 = blockIdx.x * BN;

    float acc[4][8][4];
#pragma unroll
    for (int i = 0; i < 4; i++)
#pragma unroll
        for (int j = 0; j < 8; j++)
#pragma unroll
            for (int q = 0; q < 4; q++) acc[i][j][q] = 0.f;

    // 1024 16B-chunks per tile; 128 threads -> 8 chunks of A and 8 of B each.
    auto load_tile = [&](int st, int k0) {
        __half* sA = smem + st * STAGE_ELEMS;
        __half* sB = sA + TILE;
#pragma unroll
        for (int rep = 0; rep < 8; rep++) {
            int ch  = tid + rep * NTHREADS;   // 0..1023
            int row = ch >> 3;
            int col = (ch & 7) * 8;
            size_t gA = (size_t)(bm0 + row) * K + k0 + col;
            size_t gB = (size_t)(bn0 + row) * K + k0 + col;
            int soff = row * LDS + col;
            cp_async16((uint32_t)__cvta_generic_to_shared(sA + soff), g_A + gA);
            cp_async16((uint32_t)__cvta_generic_to_shared(sB + soff), g_B + gB);
        }
    };

    load_tile(0, 0);       cp_commit();
    load_tile(1, BK);      cp_commit();

    const int NKT = K / BK;   // 64
#pragma unroll 1
    for (int kt = 0; kt < NKT; kt++) {
        cp_wait1();
        __syncthreads();

        if (kt + 2 < NKT) load_tile((kt + 2) % STAGES, (kt + 2) * BK);
        cp_commit();

        const int cur = kt % STAGES;
        const __half* sA = smem + cur * STAGE_ELEMS;
        const __half* sB = sA + TILE;

#pragma unroll
        for (int ks = 0; ks < 4; ks++) {
            const int kk = ks * 16;

            // A: 4 m16 fragments
            uint32_t af[4][4];
            const int arow = wm * 64 + (lane & 15);
            const int acol = kk + ((lane >> 4) << 3);
#pragma unroll
            for (int im = 0; im < 4; im++) {
                int soff = (arow + im * 16) * LDS + acol;
                ldm_x4(af[im], (uint32_t)__cvta_generic_to_shared(sA + soff));
            }

            // B: 8 n8 fragments via 4 x4-ldmatrix
            uint32_t bf[8][2];
            {
                int mset = lane >> 3;
                int nrow_in = (lane & 7) + ((mset >> 1) << 3);
                int col = kk + ((mset & 1) << 3);
#pragma unroll
                for (int ip = 0; ip < 4; ip++) {
                    int nrow = wn * 64 + ip * 16 + nrow_in;
                    int soff = nrow * LDS + col;
                    uint32_t r[4];
                    ldm_x4(r, (uint32_t)__cvta_generic_to_shared(sB + soff));
                    bf[ip * 2][0] = r[0]; bf[ip * 2][1] = r[1];
                    bf[ip * 2 + 1][0] = r[2]; bf[ip * 2 + 1][1] = r[3];
                }
            }

#pragma unroll
            for (int im = 0; im < 4; im++)
#pragma unroll
                for (int in = 0; in < 8; in++) mma16816(acc[im][in], af[im], bf[in]);
        }
        __syncthreads();
    }

    // Epilogue: C[m, n] -> out[m, n & 2047, n >> 11]
    const int gr = lane >> 2;
    const int gc = (lane & 3) << 1;
#pragma unroll
    for (int im = 0; im < 4; im++) {
#pragma unroll
        for (int in = 0; in < 8; in++) {
            int m0 = bm0 + wm * 64 + im * 16 + gr;
            int n0 = bn0 + wn * 64 + in * 8 + gc;
            int c = n0 >> 11;
            int o = n0 & (OUTF - 1);
            out[((size_t)m0 * OUTF + o) * 2 + c]           = acc[im][in][0];
            out[((size_t)m0 * OUTF + o + 1) * 2 + c]       = acc[im][in][1];
            out[((size_t)(m0 + 8) * OUTF + o) * 2 + c]     = acc[im][in][2];
            out[((size_t)(m0 + 8) * OUTF + o + 1) * 2 + c] = acc[im][in][3];
        }
    }
}

// ---------------------------------------------------------------------------
extern "C" void kernel_launch(void* const* d_in, const int* in_sizes, int n_in,
                              void* d_out, int out_size) {
    const float* x_re = (const float*)d_in[0];
    const float* x_im = (const float*)d_in[1];
    const float* w_re = (const float*)d_in[2];
    const float* w_im = (const float*)d_in[3];
    float* out = (float*)d_out;

    cudaFuncSetAttribute(gemm_f16, cudaFuncAttributeMaxDynamicSharedMemorySize,
                         SMEM_BYTES);

    size_t total8 = ((size_t)M * K + (size_t)N * K) / 8;
    prep_all<<<(unsigned)(total8 / 256), 256>>>(x_re, x_im, w_re, w_im);

    dim3 grid(N / BN, M / BM);
    gemm_f16<<<grid, NTHREADS, SMEM_BYTES>>>(out);
}

// round 10
// speedup vs baseline: 1.2183x; 1.2165x over previous
#include <cuda_runtime.h>
#include <cuda.h>
#include <cuda_fp16.h>
#include <cstdint>

// out[b,o,{re,im}] = complex(X) @ complex(W)^T (no conj), as ONE real GEMM:
//   C[M,N] = A[M,K] * B'[N,K]^T, M=N=K=4096
//   A = [Xre | Xim]
//   B'[n]      = [ Wre[n], -Wim[n] ]  (n<2048  -> out_re)
//   B'[n+2048] = [ Wim[n],  Wre[n] ]  (         -> out_im)
// Single fp16 product, fp32 accumulation (rel_err ~3e-4 < 1e-3).
// R10: TMA (cp.async.bulk.tensor, baseline sm_90 PTX) feeds a 3-stage
// mbarrier ring -> zero per-thread async-copy issue cost in the mainloop.

static constexpr int M = 4096;
static constexpr int N = 4096;
static constexpr int K = 4096;
static constexpr int INF = 2048;
static constexpr int OUTF = 2048;

static constexpr int BM = 128;
static constexpr int BN = 128;
static constexpr int BK = 64;                  // 64 fp16 = 128B rows (SW128 atom)
static constexpr int TILE_BYTES = BM * 128;    // 16384
static constexpr int STAGES = 3;
static constexpr int STAGE_BYTES = 2 * TILE_BYTES;   // A + B = 32768
static constexpr int SMEM_BYTES = 2048 + STAGES * STAGE_BYTES;  // 100352

static constexpr int NTHREADS = 128;

__device__ __half g_A[(size_t)M * K];
__device__ __half g_B[(size_t)N * K];

// SW128 swizzle (byte offsets within a tile; tile base 1024-aligned)
#define SW128(o) ((o) ^ (((o) >> 3) & 0x70))

// ---------------------------------------------------------------------------
// Vectorized prep: 8 elems per thread.
// ---------------------------------------------------------------------------
__global__ void prep_all(const float* __restrict__ xre, const float* __restrict__ xim,
                         const float* __restrict__ wre, const float* __restrict__ wim) {
    size_t idx8 = ((size_t)blockIdx.x * blockDim.x + threadIdx.x) * 8;
    float4 f0, f1;
    float sgn = 1.0f;
    __half* dst;

    if (idx8 < (size_t)M * K) {
        int k = (int)(idx8 & (K - 1));
        int b = (int)(idx8 >> 12);
        const float* src = (k < INF) ? (xre + (size_t)b * INF + k)
                                     : (xim + (size_t)b * INF + (k - INF));
        f0 = *(const float4*)src;
        f1 = *(const float4*)(src + 4);
        dst = g_A + idx8;
    } else {
        size_t j = idx8 - (size_t)M * K;
        int k = (int)(j & (K - 1));
        int n = (int)(j >> 12);
        const float* src;
        if (n < OUTF) {
            if (k < INF) { src = wre + (size_t)n * INF + k; }
            else         { src = wim + (size_t)n * INF + (k - INF); sgn = -1.0f; }
        } else {
            int o = n - OUTF;
            src = (k < INF) ? (wim + (size_t)o * INF + k)
                            : (wre + (size_t)o * INF + (k - INF));
        }
        f0 = *(const float4*)src;
        f1 = *(const float4*)(src + 4);
        dst = g_B + j;
    }

    __half h[8];
    h[0] = __float2half(sgn * f0.x); h[1] = __float2half(sgn * f0.y);
    h[2] = __float2half(sgn * f0.z); h[3] = __float2half(sgn * f0.w);
    h[4] = __float2half(sgn * f1.x); h[5] = __float2half(sgn * f1.y);
    h[6] = __float2half(sgn * f1.z); h[7] = __float2half(sgn * f1.w);
    *(uint4*)dst = *(const uint4*)h;
}

// ---------------------------------------------------------------------------
// helpers
// ---------------------------------------------------------------------------
__device__ __forceinline__ uint32_t smem_u32(const void* p) {
    uint32_t a;
    asm("{ .reg .u64 t; cvta.to.shared.u64 t, %1; cvt.u32.u64 %0, t; }"
        : "=r"(a) : "l"(p));
    return a;
}
#define MBARRIER_INIT(addr, cnt) \
    asm volatile("mbarrier.init.shared.b64 [%0], %1;" :: "r"(addr), "r"(cnt) : "memory")
#define MBARRIER_EXPECT_TX(addr, bytes) \
    asm volatile("mbarrier.arrive.expect_tx.shared.b64 _, [%0], %1;" \
                 :: "r"(addr), "r"(bytes) : "memory")
#define MBARRIER_WAIT_PARITY(addr, ph) do {                                   \
    uint32_t _m = (addr), _p = (ph), _d;                                      \
    asm volatile("{\n .reg .pred p;\n"                                        \
        " mbarrier.try_wait.parity.acquire.cta.shared::cta.b64 p, [%1], %2;\n"\
        " selp.b32 %0,1,0,p;\n}" : "=r"(_d) : "r"(_m), "r"(_p) : "memory");   \
    if (!_d) {                                                                \
        asm volatile("{\n .reg .pred P1;\n"                                   \
            "WL_%=:\n"                                                        \
            " mbarrier.try_wait.parity.acquire.cta.shared::cta.b64 P1, [%0], %1, 0x989680;\n" \
            " @P1 bra.uni WD_%=;\n bra.uni WL_%=;\nWD_%=:\n}"                 \
            :: "r"(_m), "r"(_p) : "memory");                                  \
    }                                                                         \
} while (0)

__device__ __forceinline__ void tma2d(uint32_t sdst, const void* map, int cx, int cy,
                                      uint32_t mbar) {
    asm volatile(
        "cp.async.bulk.tensor.2d.shared::cta.global.tile.mbarrier::complete_tx::bytes "
        "[%0], [%1, {%2, %3}], [%4];"
        :: "r"(sdst), "l"(map), "r"(cx), "r"(cy), "r"(mbar) : "memory");
}

__device__ __forceinline__ void ldm_x4(uint32_t* r, uint32_t saddr) {
    asm volatile("ldmatrix.sync.aligned.m8n8.x4.shared.b16 {%0,%1,%2,%3}, [%4];"
                 : "=r"(r[0]), "=r"(r[1]), "=r"(r[2]), "=r"(r[3]) : "r"(saddr));
}
__device__ __forceinline__ void mma16816(float* c, const uint32_t* a, const uint32_t* b) {
    asm volatile("mma.sync.aligned.m16n8k16.row.col.f32.f16.f16.f32 "
                 "{%0,%1,%2,%3}, {%4,%5,%6,%7}, {%8,%9}, {%0,%1,%2,%3};"
                 : "+f"(c[0]), "+f"(c[1]), "+f"(c[2]), "+f"(c[3])
                 : "r"(a[0]), "r"(a[1]), "r"(a[2]), "r"(a[3]),
                   "r"(b[0]), "r"(b[1]));
}

// ---------------------------------------------------------------------------
// GEMM: 128x128 CTA, 4 warps (2x2) of 64x64, BK=64, TMA 3-stage ring,
// 2 CTAs/SM. smem: [sb, sb+24) mbarriers; tiles at 1024-aligned base.
// ---------------------------------------------------------------------------
__global__ void __launch_bounds__(NTHREADS, 2) gemm_f16(
    float* __restrict__ out,
    const __grid_constant__ CUtensorMap tmA,
    const __grid_constant__ CUtensorMap tmB)
{
    extern __shared__ __align__(16) char smem[];
    uint32_t sb = smem_u32(smem);
    uint32_t tbase = (sb + 1024u) & ~1023u;    // 1024-aligned tile area

    const int tid  = threadIdx.x;
    const int lane = tid & 31;
    const int warp = tid >> 5;
    const int wm = warp >> 1;     // 0..1
    const int wn = warp & 1;      // 0..1
    const int bm0 = blockIdx.y * BM;
    const int bn0 = blockIdx.x * BN;

    if (tid == 0) {
        for (int s = 0; s < STAGES; s++) MBARRIER_INIT(sb + 8 * s, 1);
    }
    __syncthreads();

    if (tid == 0) {
#pragma unroll
        for (int s = 0; s < STAGES; s++) {
            MBARRIER_EXPECT_TX(sb + 8 * s, (uint32_t)STAGE_BYTES);
            uint32_t tb = tbase + s * STAGE_BYTES;
            tma2d(tb,              &tmA, s * BK, bm0, sb + 8 * s);
            tma2d(tb + TILE_BYTES, &tmB, s * BK, bn0, sb + 8 * s);
        }
    }

    float acc[4][8][4];
#pragma unroll
    for (int i = 0; i < 4; i++)
#pragma unroll
        for (int j = 0; j < 8; j++)
#pragma unroll
            for (int q = 0; q < 4; q++) acc[i][j][q] = 0.f;

    const int NKT = K / BK;   // 64
#pragma unroll 1
    for (int kt = 0; kt < NKT; kt++) {
        const int st = kt % STAGES;
        MBARRIER_WAIT_PARITY(sb + 8 * st, (kt / STAGES) & 1);

        const uint32_t sA = tbase + st * STAGE_BYTES;
        const uint32_t sB = sA + TILE_BYTES;

#pragma unroll
        for (int ks = 0; ks < 4; ks++) {
            const int kk = ks * 16;   // fp16 col within 64-wide tile

            // A: 4 m16 fragments (rows: wm*64 + im*16 + (lane&15), col kk + (lane>>4)*8)
            uint32_t af[4][4];
            const int arow = wm * 64 + (lane & 15);
            const int acolb = (kk + ((lane >> 4) << 3)) * 2;   // bytes
#pragma unroll
            for (int im = 0; im < 4; im++) {
                uint32_t off = (uint32_t)((arow + im * 16) * 128 + acolb);
                ldm_x4(af[im], sA + SW128(off));
            }

            // B: 8 n8 fragments via 4 x4-ldmatrix
            uint32_t bf[8][2];
            {
                int mset = lane >> 3;
                int nrow_in = (lane & 7) + ((mset >> 1) << 3);
                int colb = (kk + ((mset & 1) << 3)) * 2;
#pragma unroll
                for (int ip = 0; ip < 4; ip++) {
                    int nrow = wn * 64 + ip * 16 + nrow_in;
                    uint32_t off = (uint32_t)(nrow * 128 + colb);
                    uint32_t r[4];
                    ldm_x4(r, sB + SW128(off));
                    bf[ip * 2][0] = r[0]; bf[ip * 2][1] = r[1];
                    bf[ip * 2 + 1][0] = r[2]; bf[ip * 2 + 1][1] = r[3];
                }
            }

#pragma unroll
            for (int im = 0; im < 4; im++)
#pragma unroll
                for (int in = 0; in < 8; in++) mma16816(acc[im][in], af[im], bf[in]);
        }

        __syncthreads();   // all warps done with stage st
        if (tid == 0 && kt + STAGES < NKT) {
            MBARRIER_EXPECT_TX(sb + 8 * st, (uint32_t)STAGE_BYTES);
            uint32_t tb = tbase + st * STAGE_BYTES;
            tma2d(tb,              &tmA, (kt + STAGES) * BK, bm0, sb + 8 * st);
            tma2d(tb + TILE_BYTES, &tmB, (kt + STAGES) * BK, bn0, sb + 8 * st);
        }
    }

    // Epilogue: C[m, n] -> out[m, n & 2047, n >> 11]
    const int gr = lane >> 2;
    const int gc = (lane & 3) << 1;
#pragma unroll
    for (int im = 0; im < 4; im++) {
#pragma unroll
        for (int in = 0; in < 8; in++) {
            int m0 = bm0 + wm * 64 + im * 16 + gr;
            int n0 = bn0 + wn * 64 + in * 8 + gc;
            int c = n0 >> 11;
            int o = n0 & (OUTF - 1);
            out[((size_t)m0 * OUTF + o) * 2 + c]           = acc[im][in][0];
            out[((size_t)m0 * OUTF + o + 1) * 2 + c]       = acc[im][in][1];
            out[((size_t)(m0 + 8) * OUTF + o) * 2 + c]     = acc[im][in][2];
            out[((size_t)(m0 + 8) * OUTF + o + 1) * 2 + c] = acc[im][in][3];
        }
    }
}

// ---------------------------------------------------------------------------
// Host
// ---------------------------------------------------------------------------
typedef CUresult (*EncodeFn)(
    CUtensorMap*, CUtensorMapDataType, cuuint32_t, void*,
    const cuuint64_t*, const cuuint64_t*, const cuuint32_t*, const cuuint32_t*,
    CUtensorMapInterleave, CUtensorMapSwizzle, CUtensorMapL2promotion,
    CUtensorMapFloatOOBfill);

static void make_map(EncodeFn enc, CUtensorMap* m, void* ptr, int rows) {
    cuuint64_t dims[2]    = {(cuuint64_t)K, (cuuint64_t)rows};
    cuuint64_t strides[1] = {(cuuint64_t)K * 2};
    cuuint32_t box[2]     = {(cuuint32_t)BK, (cuuint32_t)BM};   // 64 x 128
    cuuint32_t es[2]      = {1, 1};
    enc(m, CU_TENSOR_MAP_DATA_TYPE_FLOAT16, 2, ptr, dims, strides, box, es,
        CU_TENSOR_MAP_INTERLEAVE_NONE, CU_TENSOR_MAP_SWIZZLE_128B,
        CU_TENSOR_MAP_L2_PROMOTION_L2_128B, CU_TENSOR_MAP_FLOAT_OOB_FILL_NONE);
}

extern "C" void kernel_launch(void* const* d_in, const int* in_sizes, int n_in,
                              void* d_out, int out_size) {
    const float* x_re = (const float*)d_in[0];
    const float* x_im = (const float*)d_in[1];
    const float* w_re = (const float*)d_in[2];
    const float* w_im = (const float*)d_in[3];
    float* out = (float*)d_out;

    void *pA, *pB;
    cudaGetSymbolAddress(&pA, g_A);
    cudaGetSymbolAddress(&pB, g_B);

    EncodeFn enc = nullptr;
    cudaDriverEntryPointQueryResult qr;
    cudaGetDriverEntryPointByVersion("cuTensorMapEncodeTiled", (void**)&enc, 12000,
                                     cudaEnableDefault, &qr);

    CUtensorMap mA, mB;
    make_map(enc, &mA, pA, M);
    make_map(enc, &mB, pB, N);

    cudaFuncSetAttribute(gemm_f16, cudaFuncAttributeMaxDynamicSharedMemorySize,
                         SMEM_BYTES);

    size_t total8 = ((size_t)M * K + (size_t)N * K) / 8;
    prep_all<<<(unsigned)(total8 / 256), 256>>>(x_re, x_im, w_re, w_im);

    dim3 grid(N / BN, M / BM);
    gemm_f16<<<grid, NTHREADS, SMEM_BYTES>>>(out, mA, mB);
}

// round 11
// speedup vs baseline: 1.2235x; 1.0043x over previous
#include <cuda_runtime.h>
#include <cuda.h>
#include <cuda_fp16.h>
#include <cstdint>

// out[b,o,{re,im}] = complex(X) @ complex(W)^T (no conj), as ONE real GEMM:
//   C[M,N] = A[M,K] * B'[N,K]^T, M=N=K=4096
//   A = [Xre | Xim]
//   B'[n]      = [ Wre[n], -Wim[n] ]  (n<2048  -> out_re)
//   B'[n+2048] = [ Wim[n],  Wre[n] ]  (         -> out_im)
// Single fp16 product, fp32 accumulation (rel_err ~3e-4 < 1e-3).
// R11: warp-decoupled full/empty mbarrier pipeline — NO __syncthreads in the
// mainloop; TMA reissue at iteration top with a full iteration of slack.

static constexpr int M = 4096;
static constexpr int N = 4096;
static constexpr int K = 4096;
static constexpr int INF = 2048;
static constexpr int OUTF = 2048;

static constexpr int BM = 128;
static constexpr int BN = 128;
static constexpr int BK = 64;                  // 64 fp16 = 128B rows (SW128 atom)
static constexpr int TILE_BYTES = BM * 128;    // 16384
static constexpr int STAGES = 3;
static constexpr int STAGE_BYTES = 2 * TILE_BYTES;   // A + B = 32768
static constexpr int SMEM_BYTES = 2048 + STAGES * STAGE_BYTES;  // 100352

static constexpr int NTHREADS = 128;

__device__ __half g_A[(size_t)M * K];
__device__ __half g_B[(size_t)N * K];

// SW128 swizzle (byte offsets within a tile; tile base 1024-aligned)
#define SW128(o) ((o) ^ (((o) >> 3) & 0x70))

// ---------------------------------------------------------------------------
// Vectorized prep: 8 elems per thread.
// ---------------------------------------------------------------------------
__global__ void prep_all(const float* __restrict__ xre, const float* __restrict__ xim,
                         const float* __restrict__ wre, const float* __restrict__ wim) {
    size_t idx8 = ((size_t)blockIdx.x * blockDim.x + threadIdx.x) * 8;
    float4 f0, f1;
    float sgn = 1.0f;
    __half* dst;

    if (idx8 < (size_t)M * K) {
        int k = (int)(idx8 & (K - 1));
        int b = (int)(idx8 >> 12);
        const float* src = (k < INF) ? (xre + (size_t)b * INF + k)
                                     : (xim + (size_t)b * INF + (k - INF));
        f0 = *(const float4*)src;
        f1 = *(const float4*)(src + 4);
        dst = g_A + idx8;
    } else {
        size_t j = idx8 - (size_t)M * K;
        int k = (int)(j & (K - 1));
        int n = (int)(j >> 12);
        const float* src;
        if (n < OUTF) {
            if (k < INF) { src = wre + (size_t)n * INF + k; }
            else         { src = wim + (size_t)n * INF + (k - INF); sgn = -1.0f; }
        } else {
            int o = n - OUTF;
            src = (k < INF) ? (wim + (size_t)o * INF + k)
                            : (wre + (size_t)o * INF + (k - INF));
        }
        f0 = *(const float4*)src;
        f1 = *(const float4*)(src + 4);
        dst = g_B + j;
    }

    __half h[8];
    h[0] = __float2half(sgn * f0.x); h[1] = __float2half(sgn * f0.y);
    h[2] = __float2half(sgn * f0.z); h[3] = __float2half(sgn * f0.w);
    h[4] = __float2half(sgn * f1.x); h[5] = __float2half(sgn * f1.y);
    h[6] = __float2half(sgn * f1.z); h[7] = __float2half(sgn * f1.w);
    *(uint4*)dst = *(const uint4*)h;
}

// ---------------------------------------------------------------------------
// helpers
// ---------------------------------------------------------------------------
__device__ __forceinline__ uint32_t smem_u32(const void* p) {
    uint32_t a;
    asm("{ .reg .u64 t; cvta.to.shared.u64 t, %1; cvt.u32.u64 %0, t; }"
        : "=r"(a) : "l"(p));
    return a;
}
#define MBARRIER_INIT(addr, cnt) \
    asm volatile("mbarrier.init.shared.b64 [%0], %1;" :: "r"(addr), "r"(cnt) : "memory")
#define MBARRIER_EXPECT_TX(addr, bytes) \
    asm volatile("mbarrier.arrive.expect_tx.shared.b64 _, [%0], %1;" \
                 :: "r"(addr), "r"(bytes) : "memory")
#define MBARRIER_ARRIVE(addr) \
    asm volatile("mbarrier.arrive.release.cta.shared.b64 _, [%0];" :: "r"(addr) : "memory")
#define MBARRIER_WAIT_PARITY(addr, ph) do {                                   \
    uint32_t _m = (addr), _p = (ph), _d;                                      \
    asm volatile("{\n .reg .pred p;\n"                                        \
        " mbarrier.try_wait.parity.acquire.cta.shared::cta.b64 p, [%1], %2;\n"\
        " selp.b32 %0,1,0,p;\n}" : "=r"(_d) : "r"(_m), "r"(_p) : "memory");   \
    if (!_d) {                                                                \
        asm volatile("{\n .reg .pred P1;\n"                                   \
            "WL_%=:\n"                                                        \
            " mbarrier.try_wait.parity.acquire.cta.shared::cta.b64 P1, [%0], %1, 0x989680;\n" \
            " @P1 bra.uni WD_%=;\n bra.uni WL_%=;\nWD_%=:\n}"                 \
            :: "r"(_m), "r"(_p) : "memory");                                  \
    }                                                                         \
} while (0)

__device__ __forceinline__ void tma2d(uint32_t sdst, const void* map, int cx, int cy,
                                      uint32_t mbar) {
    asm volatile(
        "cp.async.bulk.tensor.2d.shared::cta.global.tile.mbarrier::complete_tx::bytes "
        "[%0], [%1, {%2, %3}], [%4];"
        :: "r"(sdst), "l"(map), "r"(cx), "r"(cy), "r"(mbar) : "memory");
}

__device__ __forceinline__ void ldm_x4(uint32_t* r, uint32_t saddr) {
    asm volatile("ldmatrix.sync.aligned.m8n8.x4.shared.b16 {%0,%1,%2,%3}, [%4];"
                 : "=r"(r[0]), "=r"(r[1]), "=r"(r[2]), "=r"(r[3]) : "r"(saddr));
}
__device__ __forceinline__ void mma16816(float* c, const uint32_t* a, const uint32_t* b) {
    asm volatile("mma.sync.aligned.m16n8k16.row.col.f32.f16.f16.f32 "
                 "{%0,%1,%2,%3}, {%4,%5,%6,%7}, {%8,%9}, {%0,%1,%2,%3};"
                 : "+f"(c[0]), "+f"(c[1]), "+f"(c[2]), "+f"(c[3])
                 : "r"(a[0]), "r"(a[1]), "r"(a[2]), "r"(a[3]),
                   "r"(b[0]), "r"(b[1]));
}

// ---------------------------------------------------------------------------
// GEMM: 128x128 CTA, 4 warps (2x2) of 64x64, BK=64, TMA 3-stage ring,
// 2 CTAs/SM. smem layout: full[s]@ sb+8s (s<3), empty[s]@ sb+24+8s;
// tiles at 1024-aligned base.
// ---------------------------------------------------------------------------
__global__ void __launch_bounds__(NTHREADS, 2) gemm_f16(
    float* __restrict__ out,
    const __grid_constant__ CUtensorMap tmA,
    const __grid_constant__ CUtensorMap tmB)
{
    extern __shared__ __align__(16) char smem[];
    uint32_t sb = smem_u32(smem);
    uint32_t tbase = (sb + 1024u) & ~1023u;    // 1024-aligned tile area

    const int tid  = threadIdx.x;
    const int lane = tid & 31;
    const int warp = tid >> 5;
    const int wm = warp >> 1;     // 0..1
    const int wn = warp & 1;      // 0..1
    const int bm0 = blockIdx.y * BM;
    const int bn0 = blockIdx.x * BN;
    const bool producer = (tid == 0);

    if (tid == 0) {
        for (int s = 0; s < STAGES; s++) {
            MBARRIER_INIT(sb + 8 * s, 1);        // full (tx-based)
            MBARRIER_INIT(sb + 24 + 8 * s, 4);   // empty (one arrive per warp)
        }
    }
    __syncthreads();

    // prologue: fill all stages
    if (producer) {
#pragma unroll
        for (int s = 0; s < STAGES; s++) {
            MBARRIER_EXPECT_TX(sb + 8 * s, (uint32_t)STAGE_BYTES);
            uint32_t tb = tbase + s * STAGE_BYTES;
            tma2d(tb,              &tmA, s * BK, bm0, sb + 8 * s);
            tma2d(tb + TILE_BYTES, &tmB, s * BK, bn0, sb + 8 * s);
        }
    }

    float acc[4][8][4];
#pragma unroll
    for (int i = 0; i < 4; i++)
#pragma unroll
        for (int j = 0; j < 8; j++)
#pragma unroll
            for (int q = 0; q < 4; q++) acc[i][j][q] = 0.f;

    const int NKT = K / BK;   // 64
#pragma unroll 1
    for (int kt = 0; kt < NKT; kt++) {
        const int st = kt % STAGES;

        // producer: refill the stage consumed at kt-1 (data needed at kt+2)
        if (producer && kt > 0 && (kt - 1) + STAGES < NKT) {
            const int sp = (kt - 1) % STAGES;
            MBARRIER_WAIT_PARITY(sb + 24 + 8 * sp, ((kt - 1) / STAGES) & 1);
            MBARRIER_EXPECT_TX(sb + 8 * sp, (uint32_t)STAGE_BYTES);
            uint32_t tb = tbase + sp * STAGE_BYTES;
            tma2d(tb,              &tmA, ((kt - 1) + STAGES) * BK, bm0, sb + 8 * sp);
            tma2d(tb + TILE_BYTES, &tmB, ((kt - 1) + STAGES) * BK, bn0, sb + 8 * sp);
        }

        MBARRIER_WAIT_PARITY(sb + 8 * st, (kt / STAGES) & 1);

        const uint32_t sA = tbase + st * STAGE_BYTES;
        const uint32_t sB = sA + TILE_BYTES;

#pragma unroll
        for (int ks = 0; ks < 4; ks++) {
            const int kk = ks * 16;   // fp16 col within 64-wide tile

            uint32_t af[4][4];
            const int arow = wm * 64 + (lane & 15);
            const int acolb = (kk + ((lane >> 4) << 3)) * 2;
#pragma unroll
            for (int im = 0; im < 4; im++) {
                uint32_t off = (uint32_t)((arow + im * 16) * 128 + acolb);
                ldm_x4(af[im], sA + SW128(off));
            }

            uint32_t bf[8][2];
            {
                int mset = lane >> 3;
                int nrow_in = (lane & 7) + ((mset >> 1) << 3);
                int colb = (kk + ((mset & 1) << 3)) * 2;
#pragma unroll
                for (int ip = 0; ip < 4; ip++) {
                    int nrow = wn * 64 + ip * 16 + nrow_in;
                    uint32_t off = (uint32_t)(nrow * 128 + colb);
                    uint32_t r[4];
                    ldm_x4(r, sB + SW128(off));
                    bf[ip * 2][0] = r[0]; bf[ip * 2][1] = r[1];
                    bf[ip * 2 + 1][0] = r[2]; bf[ip * 2 + 1][1] = r[3];
                }
            }

#pragma unroll
            for (int im = 0; im < 4; im++)
#pragma unroll
                for (int in = 0; in < 8; in++) mma16816(acc[im][in], af[im], bf[in]);
        }

        // this warp is done with stage st
        if (lane == 0) MBARRIER_ARRIVE(sb + 24 + 8 * st);
    }

    // Epilogue: C[m, n] -> out[m, n & 2047, n >> 11]
    const int gr = lane >> 2;
    const int gc = (lane & 3) << 1;
#pragma unroll
    for (int im = 0; im < 4; im++) {
#pragma unroll
        for (int in = 0; in < 8; in++) {
            int m0 = bm0 + wm * 64 + im * 16 + gr;
            int n0 = bn0 + wn * 64 + in * 8 + gc;
            int c = n0 >> 11;
            int o = n0 & (OUTF - 1);
            out[((size_t)m0 * OUTF + o) * 2 + c]           = acc[im][in][0];
            out[((size_t)m0 * OUTF + o + 1) * 2 + c]       = acc[im][in][1];
            out[((size_t)(m0 + 8) * OUTF + o) * 2 + c]     = acc[im][in][2];
            out[((size_t)(m0 + 8) * OUTF + o + 1) * 2 + c] = acc[im][in][3];
        }
    }
}

// ---------------------------------------------------------------------------
// Host
// ---------------------------------------------------------------------------
typedef CUresult (*EncodeFn)(
    CUtensorMap*, CUtensorMapDataType, cuuint32_t, void*,
    const cuuint64_t*, const cuuint64_t*, const cuuint32_t*, const cuuint32_t*,
    CUtensorMapInterleave, CUtensorMapSwizzle, CUtensorMapL2promotion,
    CUtensorMapFloatOOBfill);

static void make_map(EncodeFn enc, CUtensorMap* m, void* ptr, int rows) {
    cuuint64_t dims[2]    = {(cuuint64_t)K, (cuuint64_t)rows};
    cuuint64_t strides[1] = {(cuuint64_t)K * 2};
    cuuint32_t box[2]     = {(cuuint32_t)BK, (cuuint32_t)BM};   // 64 x 128
    cuuint32_t es[2]      = {1, 1};
    enc(m, CU_TENSOR_MAP_DATA_TYPE_FLOAT16, 2, ptr, dims, strides, box, es,
        CU_TENSOR_MAP_INTERLEAVE_NONE, CU_TENSOR_MAP_SWIZZLE_128B,
        CU_TENSOR_MAP_L2_PROMOTION_L2_128B, CU_TENSOR_MAP_FLOAT_OOB_FILL_NONE);
}

extern "C" void kernel_launch(void* const* d_in, const int* in_sizes, int n_in,
                              void* d_out, int out_size) {
    const float* x_re = (const float*)d_in[0];
    const float* x_im = (const float*)d_in[1];
    const float* w_re = (const float*)d_in[2];
    const float* w_im = (const float*)d_in[3];
    float* out = (float*)d_out;

    void *pA, *pB;
    cudaGetSymbolAddress(&pA, g_A);
    cudaGetSymbolAddress(&pB, g_B);

    EncodeFn enc = nullptr;
    cudaDriverEntryPointQueryResult qr;
    cudaGetDriverEntryPointByVersion("cuTensorMapEncodeTiled", (void**)&enc, 12000,
                                     cudaEnableDefault, &qr);

    CUtensorMap mA, mB;
    make_map(enc, &mA, pA, M);
    make_map(enc, &mB, pB, N);

    cudaFuncSetAttribute(gemm_f16, cudaFuncAttributeMaxDynamicSharedMemorySize,
                         SMEM_BYTES);

    size_t total8 = ((size_t)M * K + (size_t)N * K) / 8;
    prep_all<<<(unsigned)(total8 / 256), 256>>>(x_re, x_im, w_re, w_im);

    dim3 grid(N / BN, M / BM);
    gemm_f16<<<grid, NTHREADS, SMEM_BYTES>>>(out, mA, mB);
}